// round 3
// baseline (speedup 1.0000x reference)
#include <cuda_runtime.h>
#include <math.h>

#define QSCALE 0.07216878364870323f   // 1/sqrt(192)
#define L2_10K 0.41524101186092024f   // log2(10000)/32

__device__ __align__(16) float g_qn[32 * 4096];
__device__ __align__(16) float g_qp[32 * 2048];
__device__ __align__(16) float g_q[32 * 32 * 576];
__device__ __align__(16) float g_num[32 * 32 * 512];
__device__ float g_den[32 * 32];
__device__ __align__(16) float g_oh[32 * 4096];

__global__ void zk(float* p, int n) {
    int i = blockIdx.x * blockDim.x + threadIdx.x;
    if (i < n) p[i] = 0.f;
}

// C[32,N] += alpha * A[32,K] @ B[K,N]; grid=(N/128, ksplit, nbatch); atomicAdd epilogue
__global__ void gemm32(const float* __restrict__ A, const float* __restrict__ B,
                       float* __restrict__ C, int K, int lda, int ldb, int ldc,
                       int Abs, int Bbs, int Cbs, float alpha)
{
    __shared__ float As[32][33];
    __shared__ float Bs[32][128];
    int bat = blockIdx.z;
    A += (long long)bat * Abs; B += (long long)bat * Bbs; C += (long long)bat * Cbs;
    int kchunk = K / gridDim.y, kbeg = blockIdx.y * kchunk;
    int n0 = blockIdx.x * 128, t = threadIdx.x;
    int tx = t & 31, ty = t >> 5;
    float acc[4][4];
#pragma unroll
    for (int i = 0; i < 4; i++)
#pragma unroll
        for (int j = 0; j < 4; j++) acc[i][j] = 0.f;

    for (int k0 = kbeg; k0 < kbeg + kchunk; k0 += 32) {
        {
            int m = t >> 3, kk = (t & 7) * 4;
            float4 a4 = *(const float4*)(A + (long long)m * lda + k0 + kk);
            As[kk][m] = a4.x; As[kk + 1][m] = a4.y; As[kk + 2][m] = a4.z; As[kk + 3][m] = a4.w;
        }
#pragma unroll
        for (int i = 0; i < 4; i++) {
            int e = t + i * 256, kk = e >> 5, c4 = (e & 31) * 4;
            *(float4*)(&Bs[kk][c4]) = *(const float4*)(B + (long long)(k0 + kk) * ldb + n0 + c4);
        }
        __syncthreads();
#pragma unroll
        for (int kk = 0; kk < 32; kk++) {
            float a0 = As[kk][ty * 4], a1 = As[kk][ty * 4 + 1], a2 = As[kk][ty * 4 + 2], a3 = As[kk][ty * 4 + 3];
            float4 b4 = *(float4*)(&Bs[kk][tx * 4]);
            acc[0][0] += a0 * b4.x; acc[0][1] += a0 * b4.y; acc[0][2] += a0 * b4.z; acc[0][3] += a0 * b4.w;
            acc[1][0] += a1 * b4.x; acc[1][1] += a1 * b4.y; acc[1][2] += a1 * b4.z; acc[1][3] += a1 * b4.w;
            acc[2][0] += a2 * b4.x; acc[2][1] += a2 * b4.y; acc[2][2] += a2 * b4.z; acc[2][3] += a2 * b4.w;
            acc[3][0] += a3 * b4.x; acc[3][1] += a3 * b4.y; acc[3][2] += a3 * b4.z; acc[3][3] += a3 * b4.w;
        }
        __syncthreads();
    }
#pragma unroll
    for (int i = 0; i < 4; i++) {
        float* dst = C + (long long)(ty * 4 + i) * ldc + n0 + tx * 4;
#pragma unroll
        for (int j = 0; j < 4; j++) atomicAdd(dst + j, alpha * acc[i][j]);
    }
}

__global__ void rope_q(const int* __restrict__ pos) {
    int b = blockIdx.x, t = threadIdx.x;
    float p = (float)pos[b];
#pragma unroll
    for (int r = 0; r < 4; r++) {
        int id = t + r * 256, h = id >> 5, i = id & 31;
        float ang = p * exp2f(-(float)i * L2_10K);
        float cv = cosf(ang), sv = sinf(ang);
        float x1 = g_qp[b * 2048 + h * 64 + i];
        float x2 = g_qp[b * 2048 + h * 64 + 32 + i];
        g_q[(b * 32 + h) * 576 + 512 + i] = (x1 * cv - x2 * sv) * QSCALE;
        g_q[(b * 32 + h) * 576 + 544 + i] = (x2 * cv + x1 * sv) * QSCALE;
    }
}

__global__ void scatter_cache(const float* __restrict__ kc, const float* __restrict__ kpe,
                              float* __restrict__ cK, float* __restrict__ cV,
                              const int* __restrict__ pos, const int* __restrict__ bidx,
                              const int* __restrict__ boff)
{
    int b = blockIdx.x, t = threadIdx.x;
    long long row = (long long)bidx[b] * 128 + boff[b];
    if (t < 32) {
        float p = (float)pos[b];
        float ang = p * exp2f(-(float)t * L2_10K);
        float cv = cosf(ang), sv = sinf(ang);
        float x1 = kpe[b * 64 + t], x2 = kpe[b * 64 + 32 + t];
        cK[row * 64 + t]      = x1 * cv - x2 * sv;
        cK[row * 64 + 32 + t] = x2 * cv + x1 * sv;
    }
    for (int j = t; j < 512; j += 128) cV[row * 512 + j] = kc[b * 512 + j];
}

#define ATTN_SMEM (28320 * 4)
__global__ void attn_kernel(const float* __restrict__ cK, const float* __restrict__ cV,
                            const int* __restrict__ blist, const int* __restrict__ bgrp,
                            const float* __restrict__ bias)
{
    extern __shared__ float sm[];
    float* q_s = sm;              // [32][576]
    float* Vc = q_s + 18432;      // [16][512]
    float* Kc = Vc + 8192;        // [16][64]
    float* p_s = Kc + 1024;       // [32][16]
    float* bias_s = p_s + 512;    // [128]
    float* den_s = bias_s + 128;  // [32]

    int n = blockIdx.x, t = threadIdx.x;
    int lane = t & 31, w = t >> 5;
    int b = bgrp[n];
    long long blk = blist[n];

    {
        const float4* src = (const float4*)(g_q + (long long)b * 18432);
        float4* dst = (float4*)q_s;
#pragma unroll
        for (int i = 0; i < 18; i++) dst[t + i * 256] = src[t + i * 256];
    }
    if (t < 128) bias_s[t] = bias[n * 128 + t];
    if (t < 32) den_s[t] = 0.f;

    int tx = t & 63, ty = t >> 6;
    float av[8][8];
#pragma unroll
    for (int j = 0; j < 8; j++)
#pragma unroll
        for (int i = 0; i < 8; i++) av[j][i] = 0.f;

    const float4* Vg = (const float4*)(cV + blk * 65536);
    const float4* Kg = (const float4*)(cK + blk * 8192);

    for (int c = 0; c < 8; c++) {
        __syncthreads();
#pragma unroll
        for (int i = 0; i < 8; i++) ((float4*)Vc)[t + i * 256] = Vg[c * 2048 + t + i * 256];
        ((float4*)Kc)[t] = Kg[c * 256 + t];
        __syncthreads();

        int h0 = w * 4;
        const float* qs0 = q_s + h0 * 576;
#pragma unroll
        for (int tt = 0; tt < 4; tt++) {
            int k0 = tt * 4;
            float acc[4][4];
#pragma unroll
            for (int i = 0; i < 4; i++)
#pragma unroll
                for (int j = 0; j < 4; j++) acc[i][j] = 0.f;
#pragma unroll
            for (int s = 0; s < 16; s++) {
                int d = s * 32 + lane;
                float qv[4], kv[4];
                qv[0] = qs0[d]; qv[1] = qs0[576 + d]; qv[2] = qs0[1152 + d]; qv[3] = qs0[1728 + d];
                kv[0] = Vc[k0 * 512 + d]; kv[1] = Vc[k0 * 512 + 512 + d];
                kv[2] = Vc[k0 * 512 + 1024 + d]; kv[3] = Vc[k0 * 512 + 1536 + d];
#pragma unroll
                for (int i = 0; i < 4; i++)
#pragma unroll
                    for (int j = 0; j < 4; j++) acc[i][j] += qv[i] * kv[j];
            }
#pragma unroll
            for (int s = 0; s < 2; s++) {
                int d = s * 32 + lane;
                float qv[4], kv[4];
                qv[0] = qs0[512 + d]; qv[1] = qs0[1088 + d]; qv[2] = qs0[1664 + d]; qv[3] = qs0[2240 + d];
                kv[0] = Kc[k0 * 64 + d]; kv[1] = Kc[k0 * 64 + 64 + d];
                kv[2] = Kc[k0 * 64 + 128 + d]; kv[3] = Kc[k0 * 64 + 192 + d];
#pragma unroll
                for (int i = 0; i < 4; i++)
#pragma unroll
                    for (int j = 0; j < 4; j++) acc[i][j] += qv[i] * kv[j];
            }
#pragma unroll
            for (int i = 0; i < 4; i++)
#pragma unroll
                for (int j = 0; j < 4; j++) {
                    float v = acc[i][j];
                    v += __shfl_xor_sync(~0u, v, 16); v += __shfl_xor_sync(~0u, v, 8);
                    v += __shfl_xor_sync(~0u, v, 4); v += __shfl_xor_sync(~0u, v, 2);
                    v += __shfl_xor_sync(~0u, v, 1);
                    acc[i][j] = v;
                }
            if (lane == 0) {
#pragma unroll
                for (int i = 0; i < 4; i++) {
                    float ds = 0.f;
#pragma unroll
                    for (int j = 0; j < 4; j++) {
                        float p = __expf(acc[i][j] + bias_s[c * 16 + k0 + j]);
                        p_s[(h0 + i) * 16 + k0 + j] = p;
                        ds += p;
                    }
                    den_s[h0 + i] += ds;
                }
            }
        }
        __syncthreads();
#pragma unroll
        for (int k = 0; k < 16; k++) {
            float4 va = ((float4*)Vc)[k * 128 + tx];
            float4 vb = ((float4*)Vc)[k * 128 + 64 + tx];
#pragma unroll
            for (int j = 0; j < 8; j++) {
                float p = p_s[(ty + j * 4) * 16 + k];
                av[j][0] += p * va.x; av[j][1] += p * va.y; av[j][2] += p * va.z; av[j][3] += p * va.w;
                av[j][4] += p * vb.x; av[j][5] += p * vb.y; av[j][6] += p * vb.z; av[j][7] += p * vb.w;
            }
        }
    }
    __syncthreads();
#pragma unroll
    for (int j = 0; j < 8; j++) {
        float* dst = g_num + (long long)(b * 32 + ty + j * 4) * 512;
#pragma unroll
        for (int i = 0; i < 4; i++) atomicAdd(dst + tx * 4 + i, av[j][i]);
#pragma unroll
        for (int i = 0; i < 4; i++) atomicAdd(dst + 256 + tx * 4 + i, av[j][4 + i]);
    }
    if (t < 32) atomicAdd(&g_den[b * 32 + t], den_s[t]);
}

__global__ void norm_kernel() {
    int i = blockIdx.x * blockDim.x + threadIdx.x;
    g_num[i] = g_num[i] / g_den[i >> 9];
}

extern "C" void kernel_launch(void* const* d_in, const int* in_sizes, int n_in,
                              void* d_out, int out_size)
{
    const float* hid  = (const float*)d_in[0];
    const float* kcn  = (const float*)d_in[1];
    const float* kpe  = (const float*)d_in[2];
    float* cacheK     = (float*)d_in[3];
    float* cacheV     = (float*)d_in[4];
    const float* W_Q  = (const float*)d_in[5];
    const float* W_UK = (const float*)d_in[6];
    const float* W_QR = (const float*)d_in[7];
    const float* W_UV = (const float*)d_in[8];
    const float* W_O  = (const float*)d_in[9];
    const int* pos    = (const int*)d_in[10];
    const int* blist  = (const int*)d_in[11];
    const int* bgrp   = (const int*)d_in[12];
    // disambiguate metadata ordering: dict order has block_bias (131072 el) at 13;
    // signature order has block_mapping (32768 el) at 13.
    int o = (in_sizes[13] == 131072) ? 0 : 1;
    const float* bias = (const float*)d_in[13 + o];
    const int* bidx   = (const int*)d_in[14 + o];
    const int* boff   = (const int*)d_in[15 + o];
    float* out = (float*)d_out;

    float *qn, *qp, *q, *num, *oh, *den;
    cudaGetSymbolAddress((void**)&qn, g_qn);
    cudaGetSymbolAddress((void**)&qp, g_qp);
    cudaGetSymbolAddress((void**)&q, g_q);
    cudaGetSymbolAddress((void**)&num, g_num);
    cudaGetSymbolAddress((void**)&oh, g_oh);
    cudaGetSymbolAddress((void**)&den, g_den);
    cudaFuncSetAttribute(attn_kernel, cudaFuncAttributeMaxDynamicSharedMemorySize, ATTN_SMEM);

    zk<<<512, 256>>>(qn, 131072);
    zk<<<256, 256>>>(qp, 65536);
    zk<<<2304, 256>>>(q, 589824);
    zk<<<2048, 256>>>(num, 524288);
    zk<<<4, 256>>>(den, 1024);
    zk<<<512, 256>>>(oh, 131072);
    zk<<<640, 256>>>(out, 163840);

    gemm32<<<dim3(32, 4, 1), 256>>>(hid, W_Q, qn, 1536, 1536, 4096, 4096, 0, 0, 0, 1.f);
    gemm32<<<dim3(16, 4, 1), 256>>>(hid, W_QR, qp, 1536, 1536, 2048, 2048, 0, 0, 0, 1.f);
    rope_q<<<32, 256>>>(pos);
    gemm32<<<dim3(4, 1, 32), 256>>>(qn, W_UK, q, 128, 4096, 512, 18432, 128, 65536, 576, QSCALE);
    scatter_cache<<<32, 128>>>(kcn, kpe, cacheK, cacheV, pos, bidx, boff);
    attn_kernel<<<1024, 256, ATTN_SMEM>>>(cacheK, cacheV, blist, bgrp, bias);
    norm_kernel<<<2048, 256>>>();
    gemm32<<<dim3(1, 4, 32), 256>>>(num, W_UV, oh, 512, 16384, 128, 4096, 512, 65536, 128, 1.f);
    gemm32<<<dim3(40, 8, 1), 256>>>(oh, W_O, out, 4096, 4096, 5120, 5120, 0, 0, 0, 1.f);
}

// round 4
// speedup vs baseline: 1.3056x; 1.3056x over previous
#include <cuda_runtime.h>
#include <math.h>

#define QSCALE 0.07216878364870323f
#define L2_10K 0.41524101186092024f
typedef unsigned long long u64;

__device__ __align__(16) float g_qn[32 * 4096];
__device__ __align__(16) float g_qp[32 * 2048];
__device__ __align__(16) float g_q[32 * 32 * 576];
__device__ __align__(16) float g_num[32 * 32 * 512];
__device__ float g_den[32 * 32];
__device__ __align__(16) float g_oh[32 * 4096];

__device__ __forceinline__ u64 pk(float a) { u64 r; asm("mov.b64 %0,{%1,%1};" : "=l"(r) : "f"(a)); return r; }
__device__ __forceinline__ void f2(u64& d, u64 a, u64 b) { asm("fma.rn.f32x2 %0,%1,%2,%0;" : "+l"(d) : "l"(a), "l"(b)); }
__device__ __forceinline__ float flo(u64 v) { return __uint_as_float((unsigned)v); }
__device__ __forceinline__ float fhi(u64 v) { return __uint_as_float((unsigned)(v >> 32)); }

__global__ void zall(float* out) {
    int i = blockIdx.x * blockDim.x + threadIdx.x, s = gridDim.x * blockDim.x;
    for (int j = i; j < 131072; j += s) { g_qn[j] = 0.f; g_oh[j] = 0.f; }
    for (int j = i; j < 65536; j += s) g_qp[j] = 0.f;
    for (int j = i; j < 589824; j += s) g_q[j] = 0.f;
    for (int j = i; j < 524288; j += s) g_num[j] = 0.f;
    for (int j = i; j < 1024; j += s) g_den[j] = 0.f;
    for (int j = i; j < 163840; j += s) out[j] = 0.f;
}

// C[32,N] += alpha*A[32,K]@B[K,N]; grid=(N/128, ksplit, nbatch)
__global__ void gemm32(const float* __restrict__ A, const float* __restrict__ B,
                       float* __restrict__ C, int K, int lda, int ldb, int ldc,
                       int Abs, int Bbs, int Cbs, float alpha)
{
    __shared__ float As[32][33];
    __shared__ __align__(16) float Bs[32][128];
    int bat = blockIdx.z;
    A += (long long)bat * Abs; B += (long long)bat * Bbs; C += (long long)bat * Cbs;
    int kchunk = K / gridDim.y, kbeg = blockIdx.y * kchunk;
    int n0 = blockIdx.x * 128, t = threadIdx.x;
    int tx = t & 31, ty = t >> 5;
    u64 acc[4][2] = {};
    for (int k0 = kbeg; k0 < kbeg + kchunk; k0 += 32) {
        {
            int m = t >> 3, kk = (t & 7) * 4;
            float4 a4 = *(const float4*)(A + (long long)m * lda + k0 + kk);
            As[kk][m] = a4.x; As[kk + 1][m] = a4.y; As[kk + 2][m] = a4.z; As[kk + 3][m] = a4.w;
        }
#pragma unroll
        for (int i = 0; i < 4; i++) {
            int e = t + i * 256, kk = e >> 5, c4 = (e & 31) * 4;
            *(float4*)(&Bs[kk][c4]) = *(const float4*)(B + (long long)(k0 + kk) * ldb + n0 + c4);
        }
        __syncthreads();
#pragma unroll
        for (int kk = 0; kk < 32; kk++) {
            u64 b0 = *(u64*)(&Bs[kk][tx * 4]), b1 = *(u64*)(&Bs[kk][tx * 4 + 2]);
#pragma unroll
            for (int i = 0; i < 4; i++) {
                u64 a = pk(As[kk][ty * 4 + i]);
                f2(acc[i][0], a, b0); f2(acc[i][1], a, b1);
            }
        }
        __syncthreads();
    }
#pragma unroll
    for (int i = 0; i < 4; i++) {
        float* dst = C + (long long)(ty * 4 + i) * ldc + n0 + tx * 4;
        atomicAdd(dst, alpha * flo(acc[i][0])); atomicAdd(dst + 1, alpha * fhi(acc[i][0]));
        atomicAdd(dst + 2, alpha * flo(acc[i][1])); atomicAdd(dst + 3, alpha * fhi(acc[i][1]));
    }
}

__global__ void rope_q(const int* __restrict__ pos) {
    int b = blockIdx.x, t = threadIdx.x;
    float p = (float)pos[b];
#pragma unroll
    for (int r = 0; r < 4; r++) {
        int id = t + r * 256, h = id >> 5, i = id & 31;
        float ang = p * exp2f(-(float)i * L2_10K);
        float cv = cosf(ang), sv = sinf(ang);
        float x1 = g_qp[b * 2048 + h * 64 + i];
        float x2 = g_qp[b * 2048 + h * 64 + 32 + i];
        g_q[(b * 32 + h) * 576 + 512 + i] = (x1 * cv - x2 * sv) * QSCALE;
        g_q[(b * 32 + h) * 576 + 544 + i] = (x2 * cv + x1 * sv) * QSCALE;
    }
}

__global__ void scatter_cache(const float* __restrict__ kc, const float* __restrict__ kpe,
                              float* __restrict__ cK, float* __restrict__ cV,
                              const int* __restrict__ pos, const int* __restrict__ bidx,
                              const int* __restrict__ boff)
{
    int b = blockIdx.x, t = threadIdx.x;
    long long row = (long long)bidx[b] * 128 + boff[b];
    if (t < 32) {
        float p = (float)pos[b];
        float ang = p * exp2f(-(float)t * L2_10K);
        float cv = cosf(ang), sv = sinf(ang);
        float x1 = kpe[b * 64 + t], x2 = kpe[b * 64 + 32 + t];
        cK[row * 64 + t] = x1 * cv - x2 * sv;
        cK[row * 64 + 32 + t] = x2 * cv + x1 * sv;
    }
    for (int j = t; j < 512; j += 128) cV[row * 512 + j] = kc[b * 512 + j];
}

#define ATTN_SMEM (28320 * 4)
__global__ void attn_kernel(const float* __restrict__ cK, const float* __restrict__ cV,
                            const int* __restrict__ blist, const int* __restrict__ bgrp,
                            const float* __restrict__ bias)
{
    extern __shared__ float sm[];
    float* q_s = sm;              // [32][576]
    float* Vc = q_s + 18432;      // [16][512]
    float* Kc = Vc + 8192;        // [16][64]
    float* p_s = Kc + 1024;       // [32][16]
    float* bias_s = p_s + 512;    // [128]
    float* den_s = bias_s + 128;  // [32]

    int n = blockIdx.x, t = threadIdx.x;
    int lane = t & 31, w = t >> 5;
    int b = bgrp[n];
    long long blk = blist[n];

    {
        const float4* src = (const float4*)(g_q + (long long)b * 18432);
        float4* dst = (float4*)q_s;
#pragma unroll
        for (int i = 0; i < 18; i++) dst[t + i * 256] = src[t + i * 256];
    }
    if (t < 128) bias_s[t] = bias[n * 128 + t];
    if (t < 32) den_s[t] = 0.f;

    int tx = t & 63, ty = t >> 6;
    u64 avp[8][4] = {};

    const float4* Vg = (const float4*)(cV + blk * 65536);
    const float4* Kg = (const float4*)(cK + blk * 8192);

    for (int c = 0; c < 8; c++) {
        __syncthreads();
#pragma unroll
        for (int i = 0; i < 8; i++) ((float4*)Vc)[t + i * 256] = Vg[c * 2048 + t + i * 256];
        ((float4*)Kc)[t] = Kg[c * 256 + t];
        __syncthreads();

        int h0 = w * 4;
        const float* qs0 = q_s + h0 * 576;
#pragma unroll
        for (int tt = 0; tt < 4; tt++) {
            int k0 = tt * 4;
            u64 acc[4][4] = {};
#pragma unroll
            for (int s = 0; s < 8; s++) {
                int d = s * 64 + lane * 2;
                u64 qv[4], kv[4];
#pragma unroll
                for (int i = 0; i < 4; i++) qv[i] = *(const u64*)(qs0 + i * 576 + d);
#pragma unroll
                for (int j = 0; j < 4; j++) kv[j] = *(const u64*)(Vc + (k0 + j) * 512 + d);
#pragma unroll
                for (int i = 0; i < 4; i++)
#pragma unroll
                    for (int j = 0; j < 4; j++) f2(acc[i][j], qv[i], kv[j]);
            }
            {
                int d = lane * 2;
                u64 qv[4], kv[4];
#pragma unroll
                for (int i = 0; i < 4; i++) qv[i] = *(const u64*)(qs0 + i * 576 + 512 + d);
#pragma unroll
                for (int j = 0; j < 4; j++) kv[j] = *(const u64*)(Kc + (k0 + j) * 64 + d);
#pragma unroll
                for (int i = 0; i < 4; i++)
#pragma unroll
                    for (int j = 0; j < 4; j++) f2(acc[i][j], qv[i], kv[j]);
            }
#pragma unroll
            for (int i = 0; i < 4; i++)
#pragma unroll
                for (int j = 0; j < 4; j++) {
                    float v = flo(acc[i][j]) + fhi(acc[i][j]);
                    v += __shfl_xor_sync(~0u, v, 16); v += __shfl_xor_sync(~0u, v, 8);
                    v += __shfl_xor_sync(~0u, v, 4); v += __shfl_xor_sync(~0u, v, 2);
                    v += __shfl_xor_sync(~0u, v, 1);
                    if (lane == 0) acc[i][j] = __float_as_uint(v);
                }
            if (lane == 0) {
#pragma unroll
                for (int i = 0; i < 4; i++) {
                    float ds = 0.f;
#pragma unroll
                    for (int j = 0; j < 4; j++) {
                        float p = __expf(flo(acc[i][j]) + bias_s[c * 16 + k0 + j]);
                        p_s[(h0 + i) * 16 + k0 + j] = p;
                        ds += p;
                    }
                    den_s[h0 + i] += ds;
                }
            }
        }
        __syncthreads();
#pragma unroll
        for (int k = 0; k < 16; k++) {
            u64 va0 = ((u64*)Vc)[k * 256 + tx * 2], va1 = ((u64*)Vc)[k * 256 + tx * 2 + 1];
            u64 vb0 = ((u64*)Vc)[k * 256 + 128 + tx * 2], vb1 = ((u64*)Vc)[k * 256 + 128 + tx * 2 + 1];
#pragma unroll
            for (int j = 0; j < 8; j++) {
                u64 pp = pk(p_s[(ty + j * 4) * 16 + k]);
                f2(avp[j][0], pp, va0); f2(avp[j][1], pp, va1);
                f2(avp[j][2], pp, vb0); f2(avp[j][3], pp, vb1);
            }
        }
    }
    __syncthreads();
#pragma unroll
    for (int j = 0; j < 8; j++) {
        float* dst = g_num + (long long)(b * 32 + ty + j * 4) * 512;
        atomicAdd(dst + tx * 4, flo(avp[j][0])); atomicAdd(dst + tx * 4 + 1, fhi(avp[j][0]));
        atomicAdd(dst + tx * 4 + 2, flo(avp[j][1])); atomicAdd(dst + tx * 4 + 3, fhi(avp[j][1]));
        atomicAdd(dst + 256 + tx * 4, flo(avp[j][2])); atomicAdd(dst + 256 + tx * 4 + 1, fhi(avp[j][2]));
        atomicAdd(dst + 256 + tx * 4 + 2, flo(avp[j][3])); atomicAdd(dst + 256 + tx * 4 + 3, fhi(avp[j][3]));
    }
    if (t < 32) atomicAdd(&g_den[b * 32 + t], den_s[t]);
}

__global__ void norm_kernel() {
    int i = blockIdx.x * blockDim.x + threadIdx.x;
    g_num[i] = g_num[i] / g_den[i >> 9];
}

extern "C" void kernel_launch(void* const* d_in, const int* in_sizes, int n_in,
                              void* d_out, int out_size)
{
    const float* hid  = (const float*)d_in[0];
    const float* kcn  = (const float*)d_in[1];
    const float* kpe  = (const float*)d_in[2];
    float* cacheK     = (float*)d_in[3];
    float* cacheV     = (float*)d_in[4];
    const float* W_Q  = (const float*)d_in[5];
    const float* W_UK = (const float*)d_in[6];
    const float* W_QR = (const float*)d_in[7];
    const float* W_UV = (const float*)d_in[8];
    const float* W_O  = (const float*)d_in[9];
    const int* pos    = (const int*)d_in[10];
    const int* blist  = (const int*)d_in[11];
    const int* bgrp   = (const int*)d_in[12];
    int o = (in_sizes[13] == 131072) ? 0 : 1;
    const float* bias = (const float*)d_in[13 + o];
    const int* bidx   = (const int*)d_in[14 + o];
    const int* boff   = (const int*)d_in[15 + o];
    float* out = (float*)d_out;

    float *qn, *qp, *q, *num, *oh;
    cudaGetSymbolAddress((void**)&qn, g_qn);
    cudaGetSymbolAddress((void**)&qp, g_qp);
    cudaGetSymbolAddress((void**)&q, g_q);
    cudaGetSymbolAddress((void**)&num, g_num);
    cudaGetSymbolAddress((void**)&oh, g_oh);
    cudaFuncSetAttribute(attn_kernel, cudaFuncAttributeMaxDynamicSharedMemorySize, ATTN_SMEM);

    zall<<<1024, 256>>>(out);
    gemm32<<<dim3(32, 4, 1), 256>>>(hid, W_Q, qn, 1536, 1536, 4096, 4096, 0, 0, 0, 1.f);
    gemm32<<<dim3(16, 4, 1), 256>>>(hid, W_QR, qp, 1536, 1536, 2048, 2048, 0, 0, 0, 1.f);
    rope_q<<<32, 256>>>(pos);
    gemm32<<<dim3(4, 1, 32), 256>>>(qn, W_UK, q, 128, 4096, 512, 18432, 128, 65536, 576, QSCALE);
    scatter_cache<<<32, 128>>>(kcn, kpe, cacheK, cacheV, pos, bidx, boff);
    attn_kernel<<<1024, 256, ATTN_SMEM>>>(cacheK, cacheV, blist, bgrp, bias);
    norm_kernel<<<2048, 256>>>();
    gemm32<<<dim3(1, 4, 32), 256>>>(num, W_UV, oh, 512, 16384, 128, 4096, 512, 65536, 128, 1.f);
    gemm32<<<dim3(40, 8, 1), 256>>>(oh, W_O, out, 4096, 4096, 5120, 5120, 0, 0, 0, 1.f);
}